// round 3
// baseline (speedup 1.0000x reference)
#include <cuda_runtime.h>
#include <cuda_bf16.h>
#include <math.h>
#include <float.h>

// ---------------- geometry ----------------
#define XDIM 2048
#define C1OUT 2046           // conv1 output spatial
#define P1 1023              // pool1 output
#define C2OUT 1021           // conv2 output spatial
#define P2 510               // pool2 output
#define S_TOT (P2*P2)        // 260100
#define KCL 12
#define CH2 16
#define BN_EPS 1e-5f

// ---------------- scratch (device globals; no allocation allowed) ----------------
__device__ float  g_h1[P1*P1*4];       // [y][x][4] interleaved (~16.7 MB)
__device__ float  g_h2[S_TOT*CH2];     // [s][16] interleaved  (~16.6 MB)
__device__ double g_stats1[8];         // sum[4], sumsq[4]
__device__ double g_stats2[32];        // sum[16], sumsq[16]
__device__ double g_vlad[KCL*CH2];     // raw sum_s a*x
__device__ double g_asum[KCL];

__device__ __forceinline__ float warp_sum(float v) {
    #pragma unroll
    for (int o = 16; o > 0; o >>= 1) v += __shfl_down_sync(0xffffffffu, v, o);
    return v;
}
__device__ __forceinline__ float sigmoidf(float x) { return 1.0f / (1.0f + expf(-x)); }

// ---------------- kernel 0: zero accumulators ----------------
__global__ void k_init() {
    int t = threadIdx.x;
    if (t < 8)   g_stats1[t] = 0.0;
    if (t < 32)  g_stats2[t] = 0.0;
    if (t < 192) g_vlad[t]   = 0.0;
    if (t < 12)  g_asum[t]   = 0.0;
}

// ---------------- kernel 1: conv1 + per-channel sum/sumsq ----------------
__global__ void k_conv1_stats(const float* __restrict__ x,
                              const float* __restrict__ w,
                              const float* __restrict__ b) {
    __shared__ float sw[108], sb[4];
    int tid = threadIdx.x;
    if (tid < 108) sw[tid] = w[tid];
    if (tid < 4)   sb[tid] = b[tid];
    __syncthreads();

    float s[4]  = {0.f, 0.f, 0.f, 0.f};
    float q[4]  = {0.f, 0.f, 0.f, 0.f};
    const int total = C1OUT * C1OUT;
    for (int idx = blockIdx.x * blockDim.x + tid; idx < total; idx += gridDim.x * blockDim.x) {
        int oy = idx / C1OUT;
        int ox = idx - oy * C1OUT;
        float a[4] = {sb[0], sb[1], sb[2], sb[3]};
        const float* xp = x + oy * XDIM + ox;
        #pragma unroll
        for (int c = 0; c < 3; c++) {
            #pragma unroll
            for (int dy = 0; dy < 3; dy++) {
                #pragma unroll
                for (int dx = 0; dx < 3; dx++) {
                    float v = __ldg(xp + c * XDIM * XDIM + dy * XDIM + dx);
                    int wi = c * 9 + dy * 3 + dx;
                    a[0] += v * sw[wi];
                    a[1] += v * sw[27 + wi];
                    a[2] += v * sw[54 + wi];
                    a[3] += v * sw[81 + wi];
                }
            }
        }
        #pragma unroll
        for (int o = 0; o < 4; o++) { s[o] += a[o]; q[o] += a[o] * a[o]; }
    }

    // block reduce 8 values, then double atomics
    __shared__ float part[8][8];
    int warp = tid >> 5, lane = tid & 31;
    float vals[8] = {s[0], s[1], s[2], s[3], q[0], q[1], q[2], q[3]};
    #pragma unroll
    for (int i = 0; i < 8; i++) {
        float r = warp_sum(vals[i]);
        if (lane == 0) part[i][warp] = r;
    }
    __syncthreads();
    if (tid < 8) {
        double t = 0.0;
        #pragma unroll
        for (int wgi = 0; wgi < 8; wgi++) t += (double)part[tid][wgi];
        atomicAdd(&g_stats1[tid], t);
    }
}

// ---------------- kernel 2: conv1 (recompute) + BN + ReLU + maxpool2 -> g_h1 ----------------
__global__ void k_conv1_bnpool(const float* __restrict__ x,
                               const float* __restrict__ w,
                               const float* __restrict__ b,
                               const float* __restrict__ gam,
                               const float* __restrict__ bet) {
    __shared__ float sw[108], sb[4], scale[4], shift[4];
    int tid = threadIdx.x;
    if (tid < 108) sw[tid] = w[tid];
    if (tid < 4) {
        sb[tid] = b[tid];
        double n    = (double)C1OUT * (double)C1OUT;
        double mean = g_stats1[tid] / n;
        double var  = g_stats1[4 + tid] / n - mean * mean;
        float sc = gam[tid] * rsqrtf((float)var + BN_EPS);
        scale[tid] = sc;
        shift[tid] = bet[tid] - (float)mean * sc;
    }
    __syncthreads();

    int idx = blockIdx.x * blockDim.x + tid;
    if (idx >= P1 * P1) return;
    int py = idx / P1;
    int px = idx - py * P1;

    // 4x4 input window per channel
    float win[3][4][4];
    const float* xp = x + (2 * py) * XDIM + 2 * px;
    #pragma unroll
    for (int c = 0; c < 3; c++)
        #pragma unroll
        for (int dy = 0; dy < 4; dy++)
            #pragma unroll
            for (int dx = 0; dx < 4; dx++)
                win[c][dy][dx] = __ldg(xp + c * XDIM * XDIM + dy * XDIM + dx);

    float out[4] = {0.f, 0.f, 0.f, 0.f};  // relu >= 0, so 0 is a safe identity
    #pragma unroll
    for (int r = 0; r < 2; r++) {
        #pragma unroll
        for (int s2 = 0; s2 < 2; s2++) {
            float a[4] = {sb[0], sb[1], sb[2], sb[3]};
            #pragma unroll
            for (int c = 0; c < 3; c++)
                #pragma unroll
                for (int dy = 0; dy < 3; dy++)
                    #pragma unroll
                    for (int dx = 0; dx < 3; dx++) {
                        float v = win[c][r + dy][s2 + dx];
                        int wi = c * 9 + dy * 3 + dx;
                        a[0] += v * sw[wi];
                        a[1] += v * sw[27 + wi];
                        a[2] += v * sw[54 + wi];
                        a[3] += v * sw[81 + wi];
                    }
            #pragma unroll
            for (int o = 0; o < 4; o++) {
                float t = fmaxf(a[o] * scale[o] + shift[o], 0.f);
                out[o] = fmaxf(out[o], t);
            }
        }
    }
    float4 o4 = make_float4(out[0], out[1], out[2], out[3]);
    *(float4*)&g_h1[idx * 4] = o4;
}

// ---------------- kernel 3: conv2 + per-channel sum/sumsq ----------------
__global__ void k_conv2_stats(const float* __restrict__ w,
                              const float* __restrict__ b) {
    __shared__ float sw[576], sb[16];
    int tid = threadIdx.x;
    for (int i = tid; i < 576; i += blockDim.x) sw[i] = w[i];
    if (tid < 16) sb[tid] = b[tid];
    __syncthreads();

    float s[16], q[16];
    #pragma unroll
    for (int o = 0; o < 16; o++) { s[o] = 0.f; q[o] = 0.f; }

    const int total = C2OUT * C2OUT;
    for (int idx = blockIdx.x * blockDim.x + tid; idx < total; idx += gridDim.x * blockDim.x) {
        int oy = idx / C2OUT;
        int ox = idx - oy * C2OUT;
        float acc[16];
        #pragma unroll
        for (int o = 0; o < 16; o++) acc[o] = sb[o];
        const float* hp = &g_h1[(oy * P1 + ox) * 4];
        #pragma unroll
        for (int dy = 0; dy < 3; dy++)
            #pragma unroll
            for (int dx = 0; dx < 3; dx++) {
                float4 v = *(const float4*)(hp + (dy * P1 + dx) * 4);
                int wb = dy * 3 + dx;
                #pragma unroll
                for (int o = 0; o < 16; o++) {
                    const float* wp = &sw[o * 36 + wb];
                    acc[o] += v.x * wp[0] + v.y * wp[9] + v.z * wp[18] + v.w * wp[27];
                }
            }
        #pragma unroll
        for (int o = 0; o < 16; o++) { s[o] += acc[o]; q[o] += acc[o] * acc[o]; }
    }

    __shared__ float part[32][8];
    int warp = tid >> 5, lane = tid & 31;
    #pragma unroll
    for (int i = 0; i < 16; i++) {
        float r = warp_sum(s[i]);
        if (lane == 0) part[i][warp] = r;
        r = warp_sum(q[i]);
        if (lane == 0) part[16 + i][warp] = r;
    }
    __syncthreads();
    if (tid < 32) {
        double t = 0.0;
        #pragma unroll
        for (int wgi = 0; wgi < 8; wgi++) t += (double)part[tid][wgi];
        atomicAdd(&g_stats2[tid], t);
    }
}

// ---------------- kernel 4: conv2 (recompute) + BN + ReLU + maxpool2 -> g_h2 ----------------
__global__ void k_conv2_bnpool(const float* __restrict__ w,
                               const float* __restrict__ b,
                               const float* __restrict__ gam,
                               const float* __restrict__ bet) {
    __shared__ float sw[576], sb[16], scale[16], shift[16];
    int tid = threadIdx.x;
    for (int i = tid; i < 576; i += blockDim.x) sw[i] = w[i];
    if (tid < 16) {
        sb[tid] = b[tid];
        double n    = (double)C2OUT * (double)C2OUT;
        double mean = g_stats2[tid] / n;
        double var  = g_stats2[16 + tid] / n - mean * mean;
        float sc = gam[tid] * rsqrtf((float)var + BN_EPS);
        scale[tid] = sc;
        shift[tid] = bet[tid] - (float)mean * sc;
    }
    __syncthreads();

    int idx = blockIdx.x * blockDim.x + tid;
    if (idx >= P2 * P2) return;
    int py = idx / P2;
    int px = idx - py * P2;

    float out[16];
    #pragma unroll
    for (int o = 0; o < 16; o++) out[o] = 0.f;

    #pragma unroll
    for (int r = 0; r < 2; r++) {
        #pragma unroll
        for (int s2 = 0; s2 < 2; s2++) {
            float acc[16];
            #pragma unroll
            for (int o = 0; o < 16; o++) acc[o] = sb[o];
            const float* hp = &g_h1[((2 * py + r) * P1 + 2 * px + s2) * 4];
            #pragma unroll
            for (int dy = 0; dy < 3; dy++)
                #pragma unroll
                for (int dx = 0; dx < 3; dx++) {
                    float4 v = *(const float4*)(hp + (dy * P1 + dx) * 4);
                    int wb = dy * 3 + dx;
                    #pragma unroll
                    for (int o = 0; o < 16; o++) {
                        const float* wp = &sw[o * 36 + wb];
                        acc[o] += v.x * wp[0] + v.y * wp[9] + v.z * wp[18] + v.w * wp[27];
                    }
                }
            #pragma unroll
            for (int o = 0; o < 16; o++) {
                float t = fmaxf(acc[o] * scale[o] + shift[o], 0.f);
                out[o] = fmaxf(out[o], t);
            }
        }
    }
    #pragma unroll
    for (int o = 0; o < 16; o += 4)
        *(float4*)&g_h2[idx * 16 + o] = make_float4(out[o], out[o + 1], out[o + 2], out[o + 3]);
}

// ---------------- kernel 5: NetVLAD soft-assign + accumulate ----------------
#define VT 256  // tile of spatial positions
__global__ void k_vlad(const float* __restrict__ aggw,
                       const float* __restrict__ aggb) {
    __shared__ float sw[KCL * CH2], sb[KCL];
    __shared__ float Xs[VT * 17];      // padded stride 17 -> conflict-free
    __shared__ float As[KCL * VT];
    int tid = threadIdx.x;
    if (tid < KCL * CH2) sw[tid] = aggw[tid];
    if (tid < KCL)       sb[tid] = aggb[tid];

    int k = tid >> 4;        // for tid < 192
    int c = tid & 15;
    float accV = 0.f;
    float accA = 0.f;

    const int ntiles = (S_TOT + VT - 1) / VT;
    __syncthreads();
    for (int tile = blockIdx.x; tile < ntiles; tile += gridDim.x) {
        int s = tile * VT + tid;
        float xv[CH2];
        float a[KCL];
        #pragma unroll
        for (int i = 0; i < CH2; i++) xv[i] = 0.f;
        #pragma unroll
        for (int i = 0; i < KCL; i++) a[i] = 0.f;

        if (s < S_TOT) {
            const float4* hp = (const float4*)&g_h2[s * CH2];
            float4 v0 = hp[0], v1 = hp[1], v2 = hp[2], v3 = hp[3];
            xv[0] = v0.x;  xv[1] = v0.y;  xv[2] = v0.z;  xv[3] = v0.w;
            xv[4] = v1.x;  xv[5] = v1.y;  xv[6] = v1.z;  xv[7] = v1.w;
            xv[8] = v2.x;  xv[9] = v2.y;  xv[10] = v2.z; xv[11] = v2.w;
            xv[12] = v3.x; xv[13] = v3.y; xv[14] = v3.z; xv[15] = v3.w;
            float mx = -FLT_MAX;
            #pragma unroll
            for (int kk = 0; kk < KCL; kk++) {
                float l = sb[kk];
                #pragma unroll
                for (int cc2 = 0; cc2 < CH2; cc2++) l += xv[cc2] * sw[kk * CH2 + cc2];
                a[kk] = l;
                mx = fmaxf(mx, l);
            }
            float sum = 0.f;
            #pragma unroll
            for (int kk = 0; kk < KCL; kk++) { a[kk] = expf(a[kk] - mx); sum += a[kk]; }
            float inv = 1.0f / sum;
            #pragma unroll
            for (int kk = 0; kk < KCL; kk++) a[kk] *= inv;
        }
        #pragma unroll
        for (int cc2 = 0; cc2 < CH2; cc2++) Xs[tid * 17 + cc2] = xv[cc2];
        #pragma unroll
        for (int kk = 0; kk < KCL; kk++) As[kk * VT + tid] = a[kk];
        __syncthreads();

        if (tid < KCL * CH2) {
            const float* ap = &As[k * VT];
            float t = 0.f;
            #pragma unroll 8
            for (int ss = 0; ss < VT; ss++) t += ap[ss] * Xs[ss * 17 + c];
            accV += t;
        }
        if (tid < KCL) {
            const float* ap = &As[tid * VT];
            float t = 0.f;
            #pragma unroll 8
            for (int ss = 0; ss < VT; ss++) t += ap[ss];
            accA += t;
        }
        __syncthreads();
    }
    if (tid < KCL * CH2) atomicAdd(&g_vlad[tid], (double)accV);
    if (tid < KCL)       atomicAdd(&g_asum[tid], (double)accA);
}

// ---------------- kernel 6: normalize + FC + LSTM (single block) ----------------
__global__ void k_final(const float* __restrict__ aggw,
                        const float* __restrict__ fcw,  const float* __restrict__ fcb,
                        const float* __restrict__ wih,  const float* __restrict__ whh,
                        const float* __restrict__ bih,  const float* __restrict__ bhh,
                        const float* __restrict__ outw, const float* __restrict__ outb,
                        const float* __restrict__ h0,   const float* __restrict__ c0,
                        const int*   __restrict__ oplen, int tmax,
                        float* __restrict__ out) {
    __shared__ float vl[192], invn[12], inp[100], hh[50], cc[50], gates[200];
    int tid = threadIdx.x;

    if (tid < 192) {
        float centre = aggw[tid] * 5.0f;  // / (2*0.1)
        vl[tid] = (float)(g_vlad[tid] - g_asum[tid >> 4] * (double)centre);
    }
    __syncthreads();
    if (tid < 12) {
        float s = 0.f;
        #pragma unroll
        for (int c = 0; c < 16; c++) { float v = vl[tid * 16 + c]; s += v * v; }
        invn[tid] = 1.0f / fmaxf(sqrtf(s), 1e-12f);
    }
    __syncthreads();
    if (tid < 192) vl[tid] *= invn[tid >> 4];
    __syncthreads();
    if (tid < 100) {
        float t = fcb[tid];
        const float* wp = &fcw[tid * 192];
        #pragma unroll 8
        for (int i = 0; i < 192; i++) t += vl[i] * wp[i];
        inp[tid] = t;
    }
    if (tid < 50) { hh[tid] = h0[tid]; cc[tid] = c0[tid]; }
    __syncthreads();

    int T = *oplen;
    if (T > tmax) T = tmax;   // never write past d_out
    if (T < 0) T = 0;
    for (int t = 0; t < T; t++) {
        if (tid < 200) {
            float g = bih[tid] + bhh[tid];
            const float* wi = &wih[tid * 100];
            #pragma unroll 4
            for (int i = 0; i < 100; i++) g += inp[i] * wi[i];
            const float* wh = &whh[tid * 50];
            #pragma unroll 5
            for (int i = 0; i < 50; i++) g += hh[i] * wh[i];
            gates[tid] = g;
        }
        __syncthreads();
        if (tid < 50) {
            float ig = sigmoidf(gates[tid]);
            float fg = sigmoidf(gates[50 + tid]);
            float gg = tanhf(gates[100 + tid]);
            float og = sigmoidf(gates[150 + tid]);
            float c2 = fg * cc[tid] + ig * gg;
            cc[tid] = c2;
            hh[tid] = og * tanhf(c2);
        }
        __syncthreads();
        if (tid < 100) {
            float o = outb[tid];
            const float* wp = &outw[tid * 50];
            #pragma unroll 5
            for (int i = 0; i < 50; i++) o += hh[i] * wp[i];
            out[t * 100 + tid] = tanhf(o);
            inp[tid] = o;  // pre-tanh fed back
        }
        __syncthreads();
    }
}

// ---------------- launcher ----------------
extern "C" void kernel_launch(void* const* d_in, const int* in_sizes, int n_in,
                              void* d_out, int out_size) {
    const float* x     = (const float*)d_in[0];
    const float* c1w   = (const float*)d_in[1];
    const float* c1b   = (const float*)d_in[2];
    const float* bn1g  = (const float*)d_in[3];
    const float* bn1b  = (const float*)d_in[4];
    const float* c2w   = (const float*)d_in[5];
    const float* c2b   = (const float*)d_in[6];
    const float* bn2g  = (const float*)d_in[7];
    const float* bn2b  = (const float*)d_in[8];
    const float* aggw  = (const float*)d_in[9];
    const float* aggb  = (const float*)d_in[10];
    const float* fcw   = (const float*)d_in[11];
    const float* fcb   = (const float*)d_in[12];
    const float* wih   = (const float*)d_in[13];
    const float* whh   = (const float*)d_in[14];
    const float* bih   = (const float*)d_in[15];
    const float* bhh   = (const float*)d_in[16];
    const float* outw  = (const float*)d_in[17];
    const float* outb  = (const float*)d_in[18];
    const float* h0    = (const float*)d_in[19];
    const float* c0    = (const float*)d_in[20];
    const int*   oplen = (const int*)  d_in[21];
    float* out = (float*)d_out;

    int tmax = out_size / 100;

    // grid sizes: multiples of 148 SMs for clean wave balance
    k_init<<<1, 256>>>();
    k_conv1_stats<<<1184, 256>>>(x, c1w, c1b);
    k_conv1_bnpool<<<(P1 * P1 + 255) / 256, 256>>>(x, c1w, c1b, bn1g, bn1b);
    k_conv2_stats<<<1184, 256>>>(c2w, c2b);
    k_conv2_bnpool<<<(P2 * P2 + 255) / 256, 256>>>(c2w, c2b, bn2g, bn2b);
    k_vlad<<<(S_TOT + VT - 1) / VT, 256>>>(aggw, aggb);
    k_final<<<1, 256>>>(aggw, fcw, fcb, wih, whh, bih, bhh, outw, outb, h0, c0, oplen, tmax, out);
}

// round 4
// speedup vs baseline: 2.0620x; 2.0620x over previous
#include <cuda_runtime.h>
#include <cuda_bf16.h>
#include <math.h>
#include <float.h>

// ---------------- geometry ----------------
#define XDIM 2048
#define C1OUT 2046           // conv1 output spatial (even: pools perfectly)
#define P1 1023              // pool1 output
#define C2OUT 1021           // conv2 output spatial (odd: border row/col for stats only)
#define PC2 511              // pool-cell grid for conv2 (covers stats border)
#define P2 510               // pool2 output
#define S_TOT (P2*P2)        // 260100
#define KCL 12
#define CH2 16
#define BN_EPS 1e-5f

// ---------------- scratch (device globals) ----------------
__device__ float  g_max1[P1*P1*4];     // pooled raw conv1 max  [cell][4]
__device__ float  g_min1[P1*P1*4];     // pooled raw conv1 min
__device__ float  g_h1[P1*P1*4];       // BN+ReLU'd pool1 output [cell][4]
__device__ float  g_max2[S_TOT*CH2];   // pooled raw conv2 max  [cell][16]
__device__ float  g_min2[S_TOT*CH2];
__device__ double g_stats1[8];         // sum[4], sumsq[4]
__device__ double g_stats2[32];        // sum[16], sumsq[16]
__device__ double g_vlad[KCL*CH2];
__device__ double g_asum[KCL];

__device__ __forceinline__ float warp_sum(float v) {
    #pragma unroll
    for (int o = 16; o > 0; o >>= 1) v += __shfl_down_sync(0xffffffffu, v, o);
    return v;
}
__device__ __forceinline__ float sigmoidf(float x) { return 1.0f / (1.0f + expf(-x)); }
// BN+ReLU on a pooled (max,min) pair: affine is monotone, pick max if scale>=0 else min
__device__ __forceinline__ float bnrelu(float M, float m, float sc, float sh) {
    float v = (sc >= 0.f) ? M : m;
    return fmaxf(fmaf(sc, v, sh), 0.f);
}

// ---------------- kernel 0: zero accumulators ----------------
__global__ void k_init() {
    int t = threadIdx.x;
    if (t < 8)   g_stats1[t] = 0.0;
    if (t < 32)  g_stats2[t] = 0.0;
    if (t < 192) g_vlad[t]   = 0.0;
    if (t < 12)  g_asum[t]   = 0.0;
}

// ---------------- kernel 1: conv1 ONE pass: stats + pooled raw max/min ----------------
__global__ __launch_bounds__(256) void k_conv1_fused(const float* __restrict__ x,
                                                     const float* __restrict__ w,
                                                     const float* __restrict__ b) {
    __shared__ float sw[108], sb[4];
    __shared__ float part[8][8];
    int tid = threadIdx.x;
    if (tid < 108) sw[tid] = w[tid];
    if (tid < 4)   sb[tid] = b[tid];
    __syncthreads();

    float s4[4] = {0.f,0.f,0.f,0.f}, q4[4] = {0.f,0.f,0.f,0.f};
    int idx = blockIdx.x * blockDim.x + tid;
    if (idx < P1 * P1) {
        int py = idx / P1;
        int px = idx - py * P1;

        float win[3][4][4];
        const float* xp = x + (2 * py) * XDIM + 2 * px;
        #pragma unroll
        for (int c = 0; c < 3; c++)
            #pragma unroll
            for (int dy = 0; dy < 4; dy++)
                #pragma unroll
                for (int dx = 0; dx < 4; dx++)
                    win[c][dy][dx] = __ldg(xp + c * XDIM * XDIM + dy * XDIM + dx);

        float mx[4], mn[4];
        #pragma unroll
        for (int o = 0; o < 4; o++) { mx[o] = -FLT_MAX; mn[o] = FLT_MAX; }

        #pragma unroll
        for (int r = 0; r < 2; r++) {
            #pragma unroll
            for (int s2 = 0; s2 < 2; s2++) {
                float a[4] = {sb[0], sb[1], sb[2], sb[3]};
                #pragma unroll
                for (int c = 0; c < 3; c++)
                    #pragma unroll
                    for (int dy = 0; dy < 3; dy++)
                        #pragma unroll
                        for (int dx = 0; dx < 3; dx++) {
                            float v = win[c][r + dy][s2 + dx];
                            int wi = c * 9 + dy * 3 + dx;
                            a[0] += v * sw[wi];
                            a[1] += v * sw[27 + wi];
                            a[2] += v * sw[54 + wi];
                            a[3] += v * sw[81 + wi];
                        }
                #pragma unroll
                for (int o = 0; o < 4; o++) {
                    s4[o] += a[o];
                    q4[o] += a[o] * a[o];
                    mx[o] = fmaxf(mx[o], a[o]);
                    mn[o] = fminf(mn[o], a[o]);
                }
            }
        }
        *(float4*)&g_max1[idx * 4] = make_float4(mx[0], mx[1], mx[2], mx[3]);
        *(float4*)&g_min1[idx * 4] = make_float4(mn[0], mn[1], mn[2], mn[3]);
    }

    int warp = tid >> 5, lane = tid & 31;
    float vals[8] = {s4[0], s4[1], s4[2], s4[3], q4[0], q4[1], q4[2], q4[3]};
    #pragma unroll
    for (int i = 0; i < 8; i++) {
        float r = warp_sum(vals[i]);
        if (lane == 0) part[i][warp] = r;
    }
    __syncthreads();
    if (tid < 8) {
        double t = 0.0;
        #pragma unroll
        for (int wg = 0; wg < 8; wg++) t += (double)part[tid][wg];
        atomicAdd(&g_stats1[tid], t);
    }
}

// ---------------- kernel 2: elementwise BN1+ReLU on pooled max/min -> g_h1 ----------------
__global__ void k_h1_bn(const float* __restrict__ gam, const float* __restrict__ bet) {
    __shared__ float sc[4], sh[4];
    int tid = threadIdx.x;
    if (tid < 4) {
        double n    = (double)C1OUT * (double)C1OUT;
        double mean = g_stats1[tid] / n;
        double var  = g_stats1[4 + tid] / n - mean * mean;
        float scl = gam[tid] * rsqrtf((float)var + BN_EPS);
        sc[tid] = scl;
        sh[tid] = bet[tid] - (float)mean * scl;
    }
    __syncthreads();
    int idx = blockIdx.x * blockDim.x + tid;
    if (idx >= P1 * P1) return;
    float4 M = *(const float4*)&g_max1[idx * 4];
    float4 m = *(const float4*)&g_min1[idx * 4];
    float4 o;
    o.x = bnrelu(M.x, m.x, sc[0], sh[0]);
    o.y = bnrelu(M.y, m.y, sc[1], sh[1]);
    o.z = bnrelu(M.z, m.z, sc[2], sh[2]);
    o.w = bnrelu(M.w, m.w, sc[3], sh[3]);
    *(float4*)&g_h1[idx * 4] = o;
}

// ---------------- kernel 3: conv2 ONE pass, channel-split (8 chans/thread) ----------------
// 2 threads per pool cell: tid<128 -> chans 0-7, tid>=128 -> chans 8-15.
// Cells cover PC2 x PC2 = 511^2 (border cells contribute stats only).
__global__ __launch_bounds__(256) void k_conv2_fused(const float* __restrict__ w,
                                                     const float* __restrict__ b) {
    __shared__ float sw[576], sb[16];
    __shared__ float part[2][16][4];
    int tid = threadIdx.x;
    for (int i = tid; i < 576; i += blockDim.x) sw[i] = w[i];
    if (tid < 16) sb[tid] = b[tid];
    __syncthreads();

    int half = tid >> 7;            // 0 or 1
    int cb   = half * 8;            // channel base
    int cell = blockIdx.x * 128 + (tid & 127);

    float s8[8], q8[8];
    #pragma unroll
    for (int o = 0; o < 8; o++) { s8[o] = 0.f; q8[o] = 0.f; }

    if (cell < PC2 * PC2) {
        int py = cell / PC2;
        int px = cell - py * PC2;
        float mx[8], mn[8];
        #pragma unroll
        for (int o = 0; o < 8; o++) { mx[o] = -FLT_MAX; mn[o] = FLT_MAX; }

        #pragma unroll
        for (int r = 0; r < 2; r++) {
            #pragma unroll
            for (int s2 = 0; s2 < 2; s2++) {
                int oy = 2 * py + r, ox = 2 * px + s2;
                if (oy < C2OUT && ox < C2OUT) {
                    float acc[8];
                    #pragma unroll
                    for (int o = 0; o < 8; o++) acc[o] = sb[cb + o];
                    const float* hp = &g_h1[(oy * P1 + ox) * 4];
                    #pragma unroll
                    for (int dy = 0; dy < 3; dy++)
                        #pragma unroll
                        for (int dx = 0; dx < 3; dx++) {
                            float4 v = *(const float4*)(hp + (dy * P1 + dx) * 4);
                            int wb = dy * 3 + dx;
                            #pragma unroll
                            for (int o = 0; o < 8; o++) {
                                const float* wp = &sw[(cb + o) * 36 + wb];
                                acc[o] += v.x * wp[0] + v.y * wp[9] + v.z * wp[18] + v.w * wp[27];
                            }
                        }
                    #pragma unroll
                    for (int o = 0; o < 8; o++) {
                        s8[o] += acc[o];
                        q8[o] += acc[o] * acc[o];
                        mx[o] = fmaxf(mx[o], acc[o]);
                        mn[o] = fminf(mn[o], acc[o]);
                    }
                }
            }
        }
        if (py < P2 && px < P2) {
            int c2 = (py * P2 + px) * CH2 + cb;
            *(float4*)&g_max2[c2]     = make_float4(mx[0], mx[1], mx[2], mx[3]);
            *(float4*)&g_max2[c2 + 4] = make_float4(mx[4], mx[5], mx[6], mx[7]);
            *(float4*)&g_min2[c2]     = make_float4(mn[0], mn[1], mn[2], mn[3]);
            *(float4*)&g_min2[c2 + 4] = make_float4(mn[4], mn[5], mn[6], mn[7]);
        }
    }

    // block reduce: warps 0-3 are half 0, warps 4-7 are half 1
    int warp = tid >> 5, lane = tid & 31;
    int wl = warp & 3, hh = warp >> 2;
    #pragma unroll
    for (int i = 0; i < 8; i++) {
        float r = warp_sum(s8[i]);
        if (lane == 0) part[hh][i][wl] = r;
        r = warp_sum(q8[i]);
        if (lane == 0) part[hh][8 + i][wl] = r;
    }
    __syncthreads();
    if (tid < 32) {
        int ch = tid & 15, isq = tid >> 4;
        int h2 = ch >> 3, c8 = ch & 7;
        float t = 0.f;
        #pragma unroll
        for (int wg = 0; wg < 4; wg++) t += part[h2][isq * 8 + c8][wg];
        atomicAdd(&g_stats2[isq * 16 + ch], (double)t);
    }
}

// ---------------- kernel 4: NetVLAD (BN2+ReLU folded into the load) ----------------
#define VT 256
__global__ void k_vlad(const float* __restrict__ aggw, const float* __restrict__ aggb,
                       const float* __restrict__ gam,  const float* __restrict__ bet) {
    __shared__ float sw[KCL * CH2], sb[KCL];
    __shared__ float sc2[CH2], sh2[CH2];
    __shared__ float Xs[VT * 17];
    __shared__ float As[KCL * VT];
    int tid = threadIdx.x;
    if (tid < KCL * CH2) sw[tid] = aggw[tid];
    if (tid < KCL)       sb[tid] = aggb[tid];
    if (tid < CH2) {
        double n    = (double)C2OUT * (double)C2OUT;
        double mean = g_stats2[tid] / n;
        double var  = g_stats2[16 + tid] / n - mean * mean;
        float scl = gam[tid] * rsqrtf((float)var + BN_EPS);
        sc2[tid] = scl;
        sh2[tid] = bet[tid] - (float)mean * scl;
    }

    int k = tid >> 4;
    int c = tid & 15;
    float accV = 0.f, accA = 0.f;

    const int ntiles = (S_TOT + VT - 1) / VT;
    __syncthreads();
    for (int tile = blockIdx.x; tile < ntiles; tile += gridDim.x) {
        int s = tile * VT + tid;
        float xv[CH2];
        float a[KCL];
        #pragma unroll
        for (int i = 0; i < CH2; i++) xv[i] = 0.f;
        #pragma unroll
        for (int i = 0; i < KCL; i++) a[i] = 0.f;

        if (s < S_TOT) {
            const float4* Mp = (const float4*)&g_max2[s * CH2];
            const float4* mp = (const float4*)&g_min2[s * CH2];
            #pragma unroll
            for (int v4 = 0; v4 < 4; v4++) {
                float4 M = Mp[v4], m = mp[v4];
                int base = v4 * 4;
                xv[base + 0] = bnrelu(M.x, m.x, sc2[base + 0], sh2[base + 0]);
                xv[base + 1] = bnrelu(M.y, m.y, sc2[base + 1], sh2[base + 1]);
                xv[base + 2] = bnrelu(M.z, m.z, sc2[base + 2], sh2[base + 2]);
                xv[base + 3] = bnrelu(M.w, m.w, sc2[base + 3], sh2[base + 3]);
            }
            float mxl = -FLT_MAX;
            #pragma unroll
            for (int kk = 0; kk < KCL; kk++) {
                float l = sb[kk];
                #pragma unroll
                for (int cc = 0; cc < CH2; cc++) l += xv[cc] * sw[kk * CH2 + cc];
                a[kk] = l;
                mxl = fmaxf(mxl, l);
            }
            float sum = 0.f;
            #pragma unroll
            for (int kk = 0; kk < KCL; kk++) { a[kk] = expf(a[kk] - mxl); sum += a[kk]; }
            float inv = 1.0f / sum;
            #pragma unroll
            for (int kk = 0; kk < KCL; kk++) a[kk] *= inv;
        }
        #pragma unroll
        for (int cc = 0; cc < CH2; cc++) Xs[tid * 17 + cc] = xv[cc];
        #pragma unroll
        for (int kk = 0; kk < KCL; kk++) As[kk * VT + tid] = a[kk];
        __syncthreads();

        if (tid < KCL * CH2) {
            const float* ap = &As[k * VT];
            float t = 0.f;
            #pragma unroll 8
            for (int ss = 0; ss < VT; ss++) t += ap[ss] * Xs[ss * 17 + c];
            accV += t;
        }
        if (tid < KCL) {
            const float* ap = &As[tid * VT];
            float t = 0.f;
            #pragma unroll 8
            for (int ss = 0; ss < VT; ss++) t += ap[ss];
            accA += t;
        }
        __syncthreads();
    }
    if (tid < KCL * CH2) atomicAdd(&g_vlad[tid], (double)accV);
    if (tid < KCL)       atomicAdd(&g_asum[tid], (double)accA);
}

// ---------------- kernel 5: normalize + FC + LSTM (single block) ----------------
__global__ void k_final(const float* __restrict__ aggw,
                        const float* __restrict__ fcw,  const float* __restrict__ fcb,
                        const float* __restrict__ wih,  const float* __restrict__ whh,
                        const float* __restrict__ bih,  const float* __restrict__ bhh,
                        const float* __restrict__ outw, const float* __restrict__ outb,
                        const float* __restrict__ h0,   const float* __restrict__ c0,
                        const int*   __restrict__ oplen, int tmax,
                        float* __restrict__ out) {
    __shared__ float vl[192], invn[12], inp[100], hh[50], cc[50], gates[200];
    int tid = threadIdx.x;

    if (tid < 192) {
        float centre = aggw[tid] * 5.0f;  // / (2*0.1)
        vl[tid] = (float)(g_vlad[tid] - g_asum[tid >> 4] * (double)centre);
    }
    __syncthreads();
    if (tid < 12) {
        float s = 0.f;
        #pragma unroll
        for (int c = 0; c < 16; c++) { float v = vl[tid * 16 + c]; s += v * v; }
        invn[tid] = 1.0f / fmaxf(sqrtf(s), 1e-12f);
    }
    __syncthreads();
    if (tid < 192) vl[tid] *= invn[tid >> 4];
    __syncthreads();
    if (tid < 100) {
        float t = fcb[tid];
        const float* wp = &fcw[tid * 192];
        #pragma unroll 8
        for (int i = 0; i < 192; i++) t += vl[i] * wp[i];
        inp[tid] = t;
    }
    if (tid < 50) { hh[tid] = h0[tid]; cc[tid] = c0[tid]; }
    __syncthreads();

    int T = *oplen;
    if (T > tmax) T = tmax;
    if (T < 0) T = 0;
    for (int t = 0; t < T; t++) {
        if (tid < 200) {
            float g = bih[tid] + bhh[tid];
            const float* wi = &wih[tid * 100];
            #pragma unroll 4
            for (int i = 0; i < 100; i++) g += inp[i] * wi[i];
            const float* wh = &whh[tid * 50];
            #pragma unroll 5
            for (int i = 0; i < 50; i++) g += hh[i] * wh[i];
            gates[tid] = g;
        }
        __syncthreads();
        if (tid < 50) {
            float ig = sigmoidf(gates[tid]);
            float fg = sigmoidf(gates[50 + tid]);
            float gg = tanhf(gates[100 + tid]);
            float og = sigmoidf(gates[150 + tid]);
            float c2 = fg * cc[tid] + ig * gg;
            cc[tid] = c2;
            hh[tid] = og * tanhf(c2);
        }
        __syncthreads();
        if (tid < 100) {
            float o = outb[tid];
            const float* wp = &outw[tid * 50];
            #pragma unroll 5
            for (int i = 0; i < 50; i++) o += hh[i] * wp[i];
            out[t * 100 + tid] = tanhf(o);
            inp[tid] = o;
        }
        __syncthreads();
    }
}

// ---------------- launcher ----------------
extern "C" void kernel_launch(void* const* d_in, const int* in_sizes, int n_in,
                              void* d_out, int out_size) {
    const float* x     = (const float*)d_in[0];
    const float* c1w   = (const float*)d_in[1];
    const float* c1b   = (const float*)d_in[2];
    const float* bn1g  = (const float*)d_in[3];
    const float* bn1b  = (const float*)d_in[4];
    const float* c2w   = (const float*)d_in[5];
    const float* c2b   = (const float*)d_in[6];
    const float* bn2g  = (const float*)d_in[7];
    const float* bn2b  = (const float*)d_in[8];
    const float* aggw  = (const float*)d_in[9];
    const float* aggb  = (const float*)d_in[10];
    const float* fcw   = (const float*)d_in[11];
    const float* fcb   = (const float*)d_in[12];
    const float* wih   = (const float*)d_in[13];
    const float* whh   = (const float*)d_in[14];
    const float* bih   = (const float*)d_in[15];
    const float* bhh   = (const float*)d_in[16];
    const float* outw  = (const float*)d_in[17];
    const float* outb  = (const float*)d_in[18];
    const float* h0    = (const float*)d_in[19];
    const float* c0    = (const float*)d_in[20];
    const int*   oplen = (const int*)  d_in[21];
    float* out = (float*)d_out;

    int tmax = out_size / 100;

    k_init<<<1, 256>>>();
    k_conv1_fused<<<(P1 * P1 + 255) / 256, 256>>>(x, c1w, c1b);
    k_h1_bn<<<(P1 * P1 + 255) / 256, 256>>>(bn1g, bn1b);
    k_conv2_fused<<<(PC2 * PC2 + 127) / 128, 256>>>(c2w, c2b);
    k_vlad<<<(S_TOT + VT - 1) / VT, 256>>>(aggw, aggb, bn2g, bn2b);
    k_final<<<1, 256>>>(aggw, fcw, fcb, wih, whh, bih, bhh, outw, outb, h0, c0, oplen, tmax, out);
}